// round 1
// baseline (speedup 1.0000x reference)
#include <cuda_runtime.h>
#include <cstdint>

// Problem constants (fixed by the reference)
#define Nn 50000
#define Ee 800000
#define Ff 128
#define Bb 64
#define EPSBN 1e-5f

// ---------------- scratch (device globals — no runtime alloc allowed) ----------
__device__ __align__(16) float d_agg[Nn * Ff];   // aggregation buffer (also pre2 in layer 2)
__device__ __align__(16) float d_h[Nn * Ff];     // pre1, then normalized+relu'd h1
__device__ float d_deg[Nn];
__device__ float d_sum[Ff];
__device__ float d_sqs[Ff];
__device__ __align__(16) float d_scale[Ff];
__device__ __align__(16) float d_shift[Ff];
__device__ __align__(16) float d_pool[Bb * Ff];
__device__ float d_cnt[Bb];

// ---------------- zero kernels -------------------------------------------------
__global__ void k_zero_a() {
    int i = blockIdx.x * blockDim.x + threadIdx.x;
    int stride = gridDim.x * blockDim.x;
    for (int j = i; j < Nn * Ff; j += stride) d_agg[j] = 0.f;
    for (int j = i; j < Nn; j += stride) d_deg[j] = 0.f;
    for (int j = i; j < Bb * Ff; j += stride) d_pool[j] = 0.f;
    if (i < Ff) { d_sum[i] = 0.f; d_sqs[i] = 0.f; }
    if (i < Bb) d_cnt[i] = 0.f;
}

__global__ void k_zero_b() {
    int i = blockIdx.x * blockDim.x + threadIdx.x;
    int stride = gridDim.x * blockDim.x;
    for (int j = i; j < Nn * Ff; j += stride) d_agg[j] = 0.f;
    if (i < Ff) { d_sum[i] = 0.f; d_sqs[i] = 0.f; }
}

// ---------------- edge scatter: warp per edge ----------------------------------
// agg[dst] += feat[src]; layer 1 also counts degree.
__global__ void k_scatter(const float* __restrict__ xin,
                          const int* __restrict__ src,
                          const int* __restrict__ dst,
                          int useH, int countDeg) {
    int e = (blockIdx.x * blockDim.x + threadIdx.x) >> 5;
    int lane = threadIdx.x & 31;
    if (e >= Ee) return;
    const float* feat = useH ? (const float*)d_h : xin;
    int s = src[e];
    int d = dst[e];
    float4 v = reinterpret_cast<const float4*>(feat)[s * 32 + lane];
    float* ap = d_agg + d * 128 + lane * 4;
    asm volatile("red.global.add.v4.f32 [%0], {%1,%2,%3,%4};"
                 :: "l"(ap), "f"(v.x), "f"(v.y), "f"(v.z), "f"(v.w) : "memory");
    if (countDeg && lane == 0) atomicAdd(d_deg + d, 1.0f);
}

// ---------------- fused dual-GEMM + bias + BN-stats ----------------------------
// pre[n,f] = sum_k (agg[n,k]/max(deg,1)) * wl[k,f] + b[f] + sum_k self[n,k] * wr[k,f]
// layer==1: self = xin, out = d_h.  layer==2: self = d_h, out = d_agg (in-place safe:
// each block stages its tile into SMEM before writing).
// Persistent blocks; weights live in SMEM; BN sum/sumsq accumulated in SMEM.
#define GEMM_THREADS 512
#define TILE_NODES 64
// smem float offsets
#define OFF_WL 0
#define OFF_WR 16384
#define OFF_A  32768
#define OFF_X  40960
#define OFF_RD 49152
#define OFF_SUM 49216
#define OFF_SQ  49344
#define SMEM_FLOATS 49472
#define SMEM_BYTES (SMEM_FLOATS * 4)

__global__ void __launch_bounds__(GEMM_THREADS, 1)
k_gemm(const float* __restrict__ xin,
       const float* __restrict__ wl, const float* __restrict__ wr,
       const float* __restrict__ bias, int layer) {
    extern __shared__ float sm[];
    float* sWl = sm + OFF_WL;
    float* sWr = sm + OFF_WR;
    float4* sA4 = reinterpret_cast<float4*>(sm + OFF_A);
    float4* sX4 = reinterpret_cast<float4*>(sm + OFF_X);
    float* sRd = sm + OFF_RD;
    float* sSum = sm + OFF_SUM;
    float* sSq = sm + OFF_SQ;

    const int tid = threadIdx.x;
    const int f = tid & 127;
    const int ng = tid >> 7;          // 0..3, 16 nodes each

    const float* self = (layer == 1) ? xin : (const float*)d_h;
    float* out = (layer == 1) ? (float*)d_h : (float*)d_agg;
    const float4* agg4 = reinterpret_cast<const float4*>(d_agg);
    const float4* self4 = reinterpret_cast<const float4*>(self);

    // load weights to SMEM (float4)
    const float4* wl4 = reinterpret_cast<const float4*>(wl);
    const float4* wr4 = reinterpret_cast<const float4*>(wr);
    for (int idx = tid; idx < 4096; idx += GEMM_THREADS) {
        reinterpret_cast<float4*>(sWl)[idx] = wl4[idx];
        reinterpret_cast<float4*>(sWr)[idx] = wr4[idx];
    }
    if (tid < 128) { sSum[tid] = 0.f; sSq[tid] = 0.f; }
    const float bf = bias[f];

    const int tiles = (Nn + TILE_NODES - 1) / TILE_NODES;
    for (int t = blockIdx.x; t < tiles; t += gridDim.x) {
        const int base = t * TILE_NODES;
        __syncthreads();               // previous tile compute done
        if (tid < TILE_NODES) {
            int n = base + tid;
            float dg = (n < Nn) ? d_deg[n] : 1.f;
            sRd[tid] = 1.f / fmaxf(dg, 1.f);
        }
        __syncthreads();
        // stage inputs: 64 nodes x 32 float4 each array
        for (int idx = tid; idx < TILE_NODES * 32; idx += GEMM_THREADS) {
            int r = idx >> 5;
            int n = base + r;
            float4 a, xv;
            if (n < Nn) {
                int c = idx & 31;
                a = agg4[n * 32 + c];
                float rd = sRd[r];
                a.x *= rd; a.y *= rd; a.z *= rd; a.w *= rd;
                xv = self4[n * 32 + c];
            } else {
                a = make_float4(0.f, 0.f, 0.f, 0.f);
                xv = a;
            }
            sA4[idx] = a;
            sX4[idx] = xv;
        }
        __syncthreads();

        float acc[16];
#pragma unroll
        for (int i = 0; i < 16; i++) acc[i] = bf;

        for (int k4 = 0; k4 < 32; k4++) {
            const int kb = k4 * 4;
            float wl0 = sWl[(kb + 0) * 128 + f];
            float wl1 = sWl[(kb + 1) * 128 + f];
            float wl2 = sWl[(kb + 2) * 128 + f];
            float wl3 = sWl[(kb + 3) * 128 + f];
            float wr0 = sWr[(kb + 0) * 128 + f];
            float wr1 = sWr[(kb + 1) * 128 + f];
            float wr2 = sWr[(kb + 2) * 128 + f];
            float wr3 = sWr[(kb + 3) * 128 + f];
#pragma unroll
            for (int i = 0; i < 16; i++) {
                const int node = ng * 16 + i;
                float4 a = sA4[node * 32 + k4];
                float4 xv = sX4[node * 32 + k4];
                float s = acc[i];
                s = fmaf(a.x, wl0, s);  s = fmaf(a.y, wl1, s);
                s = fmaf(a.z, wl2, s);  s = fmaf(a.w, wl3, s);
                s = fmaf(xv.x, wr0, s); s = fmaf(xv.y, wr1, s);
                s = fmaf(xv.z, wr2, s); s = fmaf(xv.w, wr3, s);
                acc[i] = s;
            }
        }

        float ls = 0.f, lq = 0.f;
#pragma unroll
        for (int i = 0; i < 16; i++) {
            int n = base + ng * 16 + i;
            if (n < Nn) {
                out[n * 128 + f] = acc[i];
                ls += acc[i];
                lq += acc[i] * acc[i];
            }
        }
        atomicAdd(&sSum[f], ls);
        atomicAdd(&sSq[f], lq);
    }
    __syncthreads();
    if (tid < 128) {
        atomicAdd(&d_sum[tid], sSum[tid]);
        atomicAdd(&d_sqs[tid], sSq[tid]);
    }
}

// ---------------- BN finalize: per-feature scale/shift --------------------------
__global__ void k_bnfin(const float* __restrict__ g, const float* __restrict__ beta) {
    int fidx = threadIdx.x;
    float mu = d_sum[fidx] * (1.0f / Nn);
    float var = d_sqs[fidx] * (1.0f / Nn) - mu * mu;
    float sc = g[fidx] * rsqrtf(var + EPSBN);
    d_scale[fidx] = sc;
    d_shift[fidx] = beta[fidx] - mu * sc;
}

// ---------------- normalize + relu (in place on d_h) ----------------------------
__global__ void k_nr() {
    int i = blockIdx.x * blockDim.x + threadIdx.x;
    if (i < Nn * Ff) {
        int fidx = i & 127;
        float v = d_h[i] * d_scale[fidx] + d_shift[fidx];
        d_h[i] = v > 0.f ? v : 0.f;
    }
}

// ---------------- fused norm+relu+pool: warp per node ---------------------------
__global__ void k_pool(const int* __restrict__ batch) {
    int n = (blockIdx.x * blockDim.x + threadIdx.x) >> 5;
    int lane = threadIdx.x & 31;
    if (n >= Nn) return;
    int b = batch[n];
    float4 v = reinterpret_cast<const float4*>(d_agg)[n * 32 + lane];
    float4 sc = reinterpret_cast<const float4*>(d_scale)[lane];
    float4 sh = reinterpret_cast<const float4*>(d_shift)[lane];
    v.x = fmaxf(fmaf(v.x, sc.x, sh.x), 0.f);
    v.y = fmaxf(fmaf(v.y, sc.y, sh.y), 0.f);
    v.z = fmaxf(fmaf(v.z, sc.z, sh.z), 0.f);
    v.w = fmaxf(fmaf(v.w, sc.w, sh.w), 0.f);
    float* pp = d_pool + b * 128 + lane * 4;
    asm volatile("red.global.add.v4.f32 [%0], {%1,%2,%3,%4};"
                 :: "l"(pp), "f"(v.x), "f"(v.y), "f"(v.z), "f"(v.w) : "memory");
    if (lane == 0) atomicAdd(d_cnt + b, 1.0f);
}

// ---------------- finalize: divide by counts ------------------------------------
__global__ void k_fin(float* __restrict__ out) {
    int i = blockIdx.x * blockDim.x + threadIdx.x;
    if (i < Bb * Ff) {
        float c = d_cnt[i >> 7];
        out[i] = d_pool[i] / fmaxf(c, 1.f);
    }
}

// ---------------- launcher -------------------------------------------------------
extern "C" void kernel_launch(void* const* d_in, const int* in_sizes, int n_in,
                              void* d_out, int out_size) {
    const float* x     = (const float*)d_in[0];
    const int*   ei    = (const int*)d_in[1];
    const int*   batch = (const int*)d_in[2];
    const float* wl1   = (const float*)d_in[3];
    const float* bl1   = (const float*)d_in[4];
    const float* wr1   = (const float*)d_in[5];
    const float* g1    = (const float*)d_in[6];
    const float* beta1 = (const float*)d_in[7];
    const float* wl2   = (const float*)d_in[8];
    const float* bl2   = (const float*)d_in[9];
    const float* wr2   = (const float*)d_in[10];
    const float* g2    = (const float*)d_in[11];
    const float* beta2 = (const float*)d_in[12];
    const int* src = ei;
    const int* dst = ei + Ee;
    float* out = (float*)d_out;

    cudaFuncSetAttribute(k_gemm, cudaFuncAttributeMaxDynamicSharedMemorySize, SMEM_BYTES);

    const int scatterBlocks = (Ee + 7) / 8;     // warp per edge, 8 warps/block
    const int gemmGrid = 148;

    // ---- layer 1 ----
    k_zero_a<<<2048, 256>>>();
    k_scatter<<<scatterBlocks, 256>>>(x, src, dst, /*useH=*/0, /*countDeg=*/1);
    k_gemm<<<gemmGrid, GEMM_THREADS, SMEM_BYTES>>>(x, wl1, wr1, bl1, 1);
    k_bnfin<<<1, 128>>>(g1, beta1);
    k_nr<<<(Nn * Ff + 255) / 256, 256>>>();

    // ---- layer 2 ----
    k_zero_b<<<2048, 256>>>();
    k_scatter<<<scatterBlocks, 256>>>(x, src, dst, /*useH=*/1, /*countDeg=*/0);
    k_gemm<<<gemmGrid, GEMM_THREADS, SMEM_BYTES>>>(x, wl2, wr2, bl2, 2);
    k_bnfin<<<1, 128>>>(g2, beta2);

    // ---- pool ----
    k_pool<<<(Nn + 7) / 8, 256>>>(batch);
    k_fin<<<(Bb * Ff + 255) / 256, 256>>>(out);
}

// round 4
// speedup vs baseline: 1.3117x; 1.3117x over previous
#include <cuda_runtime.h>
#include <cstdint>

#define Nn 50000
#define Ee 800000
#define Ff 128
#define Bb 64
#define EPSBN 1e-5f

// ---------------- device scratch (never passed from host!) ----------------
__device__ __align__(16) float d_agg[Nn * Ff];   // mean-agg; layer2 GEMM writes pre2 here
__device__ __align__(16) float d_h[Nn * Ff];     // pre1 (pre-BN)
__device__ int   d_cnt_i[Nn];
__device__ int   d_rowptr[Nn + 1];
__device__ int   d_cur[Nn];
__device__ int   d_esrc[Ee];
__device__ float d_sum[Ff];
__device__ float d_sqs[Ff];
__device__ __align__(16) float d_scale[Ff];
__device__ __align__(16) float d_shift[Ff];
__device__ __align__(16) float d_pool[Bb * Ff];
__device__ float d_cnt[Bb];

#define FMA2(acc, a, b) asm("fma.rn.f32x2 %0, %1, %2, %0;" : "+l"(acc) : "l"(a), "l"(b))

// ---------------- zero small stuff ----------------
__global__ void k_zero() {
    int i = blockIdx.x * blockDim.x + threadIdx.x;
    int stride = gridDim.x * blockDim.x;
    for (int j = i; j < Nn; j += stride) d_cnt_i[j] = 0;
    for (int j = i; j < Bb * Ff; j += stride) d_pool[j] = 0.f;
    if (i < Ff) { d_sum[i] = 0.f; d_sqs[i] = 0.f; }
    if (i < Bb) d_cnt[i] = 0.f;
}

// ---------------- CSR build ----------------
__global__ void k_count(const int* __restrict__ dst) {
    int e = blockIdx.x * blockDim.x + threadIdx.x;
    if (e < Ee) atomicAdd(&d_cnt_i[dst[e]], 1);
}

__global__ void k_scan() {
    __shared__ int ps[1024];
    const int t = threadIdx.x;
    const int CH = 49;   // 49*1024 = 50176 >= Nn
    int base = t * CH;
    int s = 0;
    for (int i = 0; i < CH; i++) {
        int idx = base + i;
        if (idx < Nn) s += d_cnt_i[idx];
    }
    ps[t] = s;
    __syncthreads();
    for (int off = 1; off < 1024; off <<= 1) {
        int v = (t >= off) ? ps[t - off] : 0;
        __syncthreads();
        ps[t] += v;
        __syncthreads();
    }
    int run = ps[t] - s;   // exclusive prefix
    for (int i = 0; i < CH; i++) {
        int idx = base + i;
        if (idx < Nn) {
            d_rowptr[idx] = run;
            d_cur[idx] = run;
            run += d_cnt_i[idx];
        }
    }
    if (t == 1023) d_rowptr[Nn] = Ee;
}

__global__ void k_fill(const int* __restrict__ src, const int* __restrict__ dst) {
    int e = blockIdx.x * blockDim.x + threadIdx.x;
    if (e < Ee) {
        int pos = atomicAdd(&d_cur[dst[e]], 1);
        d_esrc[pos] = src[e];
    }
}

// ---------------- pull gather: warp per node, mean aggregation ------------------
// useH: feat = d_h (device-side select!). norm: apply BN scale/shift + relu on the fly.
__global__ void k_gather(const float* __restrict__ xin, int useH, int norm) {
    int n = (blockIdx.x * blockDim.x + threadIdx.x) >> 5;
    int lane = threadIdx.x & 31;
    if (n >= Nn) return;
    const float* feat = useH ? (const float*)d_h : xin;
    const float4* f4 = reinterpret_cast<const float4*>(feat);
    int j = d_rowptr[n];
    const int jend = d_rowptr[n + 1];
    const int deg = jend - j;
    float4 acc = make_float4(0.f, 0.f, 0.f, 0.f);
    float4 sc, sh;
    if (norm) {
        sc = reinterpret_cast<const float4*>(d_scale)[lane];
        sh = reinterpret_cast<const float4*>(d_shift)[lane];
    }
    for (; j + 4 <= jend; j += 4) {
        int e0 = d_esrc[j], e1 = d_esrc[j + 1], e2 = d_esrc[j + 2], e3 = d_esrc[j + 3];
        float4 v0 = f4[e0 * 32 + lane];
        float4 v1 = f4[e1 * 32 + lane];
        float4 v2 = f4[e2 * 32 + lane];
        float4 v3 = f4[e3 * 32 + lane];
        if (norm) {
            v0.x = fmaxf(fmaf(v0.x, sc.x, sh.x), 0.f); v0.y = fmaxf(fmaf(v0.y, sc.y, sh.y), 0.f);
            v0.z = fmaxf(fmaf(v0.z, sc.z, sh.z), 0.f); v0.w = fmaxf(fmaf(v0.w, sc.w, sh.w), 0.f);
            v1.x = fmaxf(fmaf(v1.x, sc.x, sh.x), 0.f); v1.y = fmaxf(fmaf(v1.y, sc.y, sh.y), 0.f);
            v1.z = fmaxf(fmaf(v1.z, sc.z, sh.z), 0.f); v1.w = fmaxf(fmaf(v1.w, sc.w, sh.w), 0.f);
            v2.x = fmaxf(fmaf(v2.x, sc.x, sh.x), 0.f); v2.y = fmaxf(fmaf(v2.y, sc.y, sh.y), 0.f);
            v2.z = fmaxf(fmaf(v2.z, sc.z, sh.z), 0.f); v2.w = fmaxf(fmaf(v2.w, sc.w, sh.w), 0.f);
            v3.x = fmaxf(fmaf(v3.x, sc.x, sh.x), 0.f); v3.y = fmaxf(fmaf(v3.y, sc.y, sh.y), 0.f);
            v3.z = fmaxf(fmaf(v3.z, sc.z, sh.z), 0.f); v3.w = fmaxf(fmaf(v3.w, sc.w, sh.w), 0.f);
        }
        acc.x += v0.x + v1.x + v2.x + v3.x;
        acc.y += v0.y + v1.y + v2.y + v3.y;
        acc.z += v0.z + v1.z + v2.z + v3.z;
        acc.w += v0.w + v1.w + v2.w + v3.w;
    }
    for (; j < jend; j++) {
        int e0 = d_esrc[j];
        float4 v0 = f4[e0 * 32 + lane];
        if (norm) {
            v0.x = fmaxf(fmaf(v0.x, sc.x, sh.x), 0.f); v0.y = fmaxf(fmaf(v0.y, sc.y, sh.y), 0.f);
            v0.z = fmaxf(fmaf(v0.z, sc.z, sh.z), 0.f); v0.w = fmaxf(fmaf(v0.w, sc.w, sh.w), 0.f);
        }
        acc.x += v0.x; acc.y += v0.y; acc.z += v0.z; acc.w += v0.w;
    }
    float inv = 1.f / fmaxf((float)deg, 1.f);
    acc.x *= inv; acc.y *= inv; acc.z *= inv; acc.w *= inv;
    reinterpret_cast<float4*>(d_agg)[n * 32 + lane] = acc;
}

// ---------------- fused dual-GEMM (packed fma.f32x2) + bias + BN-stats ------------
// out[n,f] = sum_k agg[n,k]*wl[k,f] + sum_k self[n,k]*wr[k,f] + b[f]
// layer==1: self = xin (harness ptr), out = d_h.
// layer==2: self = d_h (device-side select) with BN+relu at staging, out = d_agg.
#define GEMM_THREADS 512
#define TILE_NODES 64
#define OFF_W   0                      // 128k * 128f * 2 = 32768 floats (interleaved wl/wr)
#define OFF_AX  32768                  // 64n * 128k * 2  = 16384 floats (interleaved agg/self)
#define OFF_SUM 49152
#define OFF_SQ  49280
#define SMEM_FLOATS 49408
#define SMEM_BYTES (SMEM_FLOATS * 4)

__global__ void __launch_bounds__(GEMM_THREADS, 1)
k_gemm(const float* __restrict__ xin,
       const float* __restrict__ wl, const float* __restrict__ wr,
       const float* __restrict__ bias, int layer) {
    extern __shared__ float sm[];
    float* sW  = sm + OFF_W;
    float* sAX = sm + OFF_AX;
    float* sSum = sm + OFF_SUM;
    float* sSq  = sm + OFF_SQ;

    const int tid = threadIdx.x;
    const int fc = tid & 63;          // feature pair: features 2fc, 2fc+1
    const int nb = (tid >> 6) * 8;    // node group base within tile (8 nodes)

    const float* self = (layer == 1) ? xin : (const float*)d_h;
    float* out = (layer == 1) ? (float*)d_h : (float*)d_agg;
    const float4* agg4  = reinterpret_cast<const float4*>(d_agg);
    const float4* self4 = reinterpret_cast<const float4*>(self);
    const float4* sc4 = reinterpret_cast<const float4*>(d_scale);
    const float4* sh4 = reinterpret_cast<const float4*>(d_shift);

    // stage weights interleaved: sW[k*256 + 2f + {0:wl,1:wr}]
    {
        const float4* wl4 = reinterpret_cast<const float4*>(wl);
        const float4* wr4 = reinterpret_cast<const float4*>(wr);
        float4* sW4 = reinterpret_cast<float4*>(sW);
        for (int idx = tid; idx < 4096; idx += GEMM_THREADS) {
            float4 a = wl4[idx];
            float4 b = wr4[idx];
            int k = idx >> 5, c = idx & 31;
            sW4[k * 64 + 2 * c]     = make_float4(a.x, b.x, a.y, b.y);
            sW4[k * 64 + 2 * c + 1] = make_float4(a.z, b.z, a.w, b.w);
        }
    }
    if (tid < 128) { sSum[tid] = 0.f; sSq[tid] = 0.f; }

    const float2 b2 = *reinterpret_cast<const float2*>(&bias[2 * fc]);
    float ls0 = 0.f, lq0 = 0.f, ls1 = 0.f, lq1 = 0.f;

    const int tiles = (Nn + TILE_NODES - 1) / TILE_NODES;
    for (int t = blockIdx.x; t < tiles; t += gridDim.x) {
        const int base = t * TILE_NODES;
        __syncthreads();   // prev tile compute done; also covers weight staging
        // stage data interleaved: sAX[n*256 + 2k + {0:agg,1:self}]
        {
            float4* sAX4 = reinterpret_cast<float4*>(sAX);
            for (int idx = tid; idx < TILE_NODES * 32; idx += GEMM_THREADS) {
                int r = idx >> 5, c = idx & 31;
                int n = base + r;
                float4 a = make_float4(0.f, 0.f, 0.f, 0.f);
                float4 xv = a;
                if (n < Nn) {
                    a  = agg4[n * 32 + c];
                    xv = self4[n * 32 + c];
                    if (layer == 2) {
                        float4 sc = sc4[c], sh = sh4[c];
                        xv.x = fmaxf(fmaf(xv.x, sc.x, sh.x), 0.f);
                        xv.y = fmaxf(fmaf(xv.y, sc.y, sh.y), 0.f);
                        xv.z = fmaxf(fmaf(xv.z, sc.z, sh.z), 0.f);
                        xv.w = fmaxf(fmaf(xv.w, sc.w, sh.w), 0.f);
                    }
                }
                sAX4[r * 64 + 2 * c]     = make_float4(a.x, xv.x, a.y, xv.y);
                sAX4[r * 64 + 2 * c + 1] = make_float4(a.z, xv.z, a.w, xv.w);
            }
        }
        __syncthreads();

        // compute: 8 nodes x 2 features per thread, packed f32x2
        unsigned long long acc[16];
#pragma unroll
        for (int i = 0; i < 16; i++) acc[i] = 0ull;

#pragma unroll 8
        for (int k2 = 0; k2 < 64; k2++) {
            ulonglong2 wA = *reinterpret_cast<const ulonglong2*>(&sW[k2 * 512 + 4 * fc]);
            ulonglong2 wB = *reinterpret_cast<const ulonglong2*>(&sW[k2 * 512 + 256 + 4 * fc]);
#pragma unroll
            for (int i = 0; i < 8; i++) {
                ulonglong2 dv = *reinterpret_cast<const ulonglong2*>(&sAX[(nb + i) * 256 + 4 * k2]);
                FMA2(acc[i * 2 + 0], dv.x, wA.x);
                FMA2(acc[i * 2 + 1], dv.x, wA.y);
                FMA2(acc[i * 2 + 0], dv.y, wB.x);
                FMA2(acc[i * 2 + 1], dv.y, wB.y);
            }
        }

        // epilogue: combine halves + bias, store, BN stats
#pragma unroll
        for (int i = 0; i < 8; i++) {
            int n = base + nb + i;
            if (n < Nn) {
                unsigned long long a0 = acc[i * 2 + 0], a1 = acc[i * 2 + 1];
                float v0 = __uint_as_float((unsigned)a0) + __uint_as_float((unsigned)(a0 >> 32)) + b2.x;
                float v1 = __uint_as_float((unsigned)a1) + __uint_as_float((unsigned)(a1 >> 32)) + b2.y;
                *reinterpret_cast<float2*>(&out[n * 128 + 2 * fc]) = make_float2(v0, v1);
                ls0 += v0; lq0 += v0 * v0;
                ls1 += v1; lq1 += v1 * v1;
            }
        }
    }
    // flush BN stats
    atomicAdd(&sSum[2 * fc], ls0);
    atomicAdd(&sSum[2 * fc + 1], ls1);
    atomicAdd(&sSq[2 * fc], lq0);
    atomicAdd(&sSq[2 * fc + 1], lq1);
    __syncthreads();
    if (tid < 128) {
        atomicAdd(&d_sum[tid], sSum[tid]);
        atomicAdd(&d_sqs[tid], sSq[tid]);
    }
}

// ---------------- BN finalize (also resets stats for next layer) -----------------
__global__ void k_bnfin(const float* __restrict__ g, const float* __restrict__ beta) {
    int fidx = threadIdx.x;
    float mu = d_sum[fidx] * (1.0f / Nn);
    float var = d_sqs[fidx] * (1.0f / Nn) - mu * mu;
    float sc = g[fidx] * rsqrtf(var + EPSBN);
    d_scale[fidx] = sc;
    d_shift[fidx] = beta[fidx] - mu * sc;
    d_sum[fidx] = 0.f;
    d_sqs[fidx] = 0.f;
}

// ---------------- fused norm+relu+pool: warp per node ----------------------------
__global__ void k_pool(const int* __restrict__ batch) {
    int n = (blockIdx.x * blockDim.x + threadIdx.x) >> 5;
    int lane = threadIdx.x & 31;
    if (n >= Nn) return;
    int b = batch[n];
    float4 v = reinterpret_cast<const float4*>(d_agg)[n * 32 + lane];
    float4 sc = reinterpret_cast<const float4*>(d_scale)[lane];
    float4 sh = reinterpret_cast<const float4*>(d_shift)[lane];
    v.x = fmaxf(fmaf(v.x, sc.x, sh.x), 0.f);
    v.y = fmaxf(fmaf(v.y, sc.y, sh.y), 0.f);
    v.z = fmaxf(fmaf(v.z, sc.z, sh.z), 0.f);
    v.w = fmaxf(fmaf(v.w, sc.w, sh.w), 0.f);
    float* pp = d_pool + b * 128 + lane * 4;
    asm volatile("red.global.add.v4.f32 [%0], {%1,%2,%3,%4};"
                 :: "l"(pp), "f"(v.x), "f"(v.y), "f"(v.z), "f"(v.w) : "memory");
    if (lane == 0) atomicAdd(d_cnt + b, 1.0f);
}

__global__ void k_fin(float* __restrict__ out) {
    int i = blockIdx.x * blockDim.x + threadIdx.x;
    if (i < Bb * Ff) {
        float c = d_cnt[i >> 7];
        out[i] = d_pool[i] / fmaxf(c, 1.f);
    }
}

// ---------------- launcher --------------------------------------------------------
extern "C" void kernel_launch(void* const* d_in, const int* in_sizes, int n_in,
                              void* d_out, int out_size) {
    const float* x     = (const float*)d_in[0];
    const int*   ei    = (const int*)d_in[1];
    const int*   batch = (const int*)d_in[2];
    const float* wl1   = (const float*)d_in[3];
    const float* bl1   = (const float*)d_in[4];
    const float* wr1   = (const float*)d_in[5];
    const float* g1    = (const float*)d_in[6];
    const float* beta1 = (const float*)d_in[7];
    const float* wl2   = (const float*)d_in[8];
    const float* bl2   = (const float*)d_in[9];
    const float* wr2   = (const float*)d_in[10];
    const float* g2    = (const float*)d_in[11];
    const float* beta2 = (const float*)d_in[12];
    const int* src = ei;
    const int* dst = ei + Ee;
    float* out = (float*)d_out;

    cudaFuncSetAttribute(k_gemm, cudaFuncAttributeMaxDynamicSharedMemorySize, SMEM_BYTES);

    const int edgeBlocks = (Ee + 255) / 256;
    const int gatherBlocks = (Nn * 32 + 255) / 256;

    // CSR build (shared by both layers)
    k_zero<<<512, 256>>>();
    k_count<<<edgeBlocks, 256>>>(dst);
    k_scan<<<1, 1024>>>();
    k_fill<<<edgeBlocks, 256>>>(src, dst);

    // ---- layer 1 ----
    k_gather<<<gatherBlocks, 256>>>(x, /*useH=*/0, /*norm=*/0);
    k_gemm<<<148, GEMM_THREADS, SMEM_BYTES>>>(x, wl1, wr1, bl1, 1);
    k_bnfin<<<1, 128>>>(g1, beta1);

    // ---- layer 2 ----
    k_gather<<<gatherBlocks, 256>>>(x, /*useH=*/1, /*norm=*/1);
    k_gemm<<<148, GEMM_THREADS, SMEM_BYTES>>>(x, wl2, wr2, bl2, 2);
    k_bnfin<<<1, 128>>>(g2, beta2);

    // ---- pool ----
    k_pool<<<(Nn + 7) / 8, 256>>>(batch);
    k_fin<<<32, 256>>>(out);
}